// round 10
// baseline (speedup 1.0000x reference)
#include <cuda_runtime.h>
#include <cstdint>

// Problem constants (fixed by the dataset)
#define T_ 8
#define E_ 8388608
#define N_ 262144
#define F_ 64

// 8 MB scratch for segment sums, layout agg[n][t] row-major (32B per node).
// Zero-initialized at module load; gemm_kernel re-zeros it after consuming,
// so every launch (and every graph replay) starts from zeros — no separate
// zero kernel (its 5us serial launch cost exceeded its L2-warmth benefit).
__device__ float g_agg[(size_t)N_ * T_];

// ---------------------------------------------------------------------------
// Scatter-add. Warp = 32 edges. Lane pair (2p, 2p+1) handles edges eA, eB:
// even lane covers feature planes 0..3, odd lane 4..7, each loading float2
// {eA,eB} per plane (fully-consumed 128B lines). Rows swapped via SHFL.
// Each RED instruction's lane pairs cover one full 32B agg row -> 16 lines
// per RED instr (minimum possible: 1 line-wavefront per edge).
// ---------------------------------------------------------------------------
__global__ void scatter_kernel(const float* __restrict__ feat,
                               const int2* __restrict__ idx) {
    int tid   = blockIdx.x * blockDim.x + threadIdx.x;
    int lane  = threadIdx.x & 31;
    int h     = lane & 1;                 // 0: planes 0..3, 1: planes 4..7
    int ebase = (tid >> 5) * 32;          // warp's first edge
    int eA    = ebase + (lane & ~1);      // pair's even edge

    int2 rc = __ldcs(&idx[ebase + lane]); // coalesced 256B/warp
    int row = rc.x & (N_ - 1);            // pow2 mask: no-op for valid rows

    int rA = __shfl_sync(0xffffffffu, row, lane & ~1);
    int rB = __shfl_sync(0xffffffffu, row, lane | 1);

    size_t plane = (size_t)(4 * h) * E_ + eA;
    float2 l0 = __ldcs(reinterpret_cast<const float2*>(feat + plane));
    float2 l1 = __ldcs(reinterpret_cast<const float2*>(feat + plane + (size_t)E_));
    float2 l2 = __ldcs(reinterpret_cast<const float2*>(feat + plane + (size_t)2 * E_));
    float2 l3 = __ldcs(reinterpret_cast<const float2*>(feat + plane + (size_t)3 * E_));

    float* dA = g_agg + (size_t)rA * T_ + 4 * h;
    asm volatile("red.global.add.v4.f32 [%0], {%1,%2,%3,%4};"
                 :: "l"(dA), "f"(l0.x), "f"(l1.x), "f"(l2.x), "f"(l3.x) : "memory");

    float* dB = g_agg + (size_t)rB * T_ + 4 * h;
    asm volatile("red.global.add.v4.f32 [%0], {%1,%2,%3,%4};"
                 :: "l"(dB), "f"(l0.y), "f"(l1.y), "f"(l2.y), "f"(l3.y) : "memory");
}

// ---------------------------------------------------------------------------
// GEMM: out[n,f] = sum_t agg[n,t]*K[t,f] + bias[f], plus consume-and-zero of
// agg for the next replay. 16384 warps; K slice in registers (loaded once),
// 8 iters x 2 nodes with the next agg row prefetched before computing the
// current one. Zero-stores target already-computed rows (no hazard with the
// prefetch) and overlap the DRAM-bound output writes.
// ---------------------------------------------------------------------------
#define GEMM_WARPS 16384
#define GEMM_ITERS (N_ / (GEMM_WARPS * 2))   // 8

__global__ void gemm_kernel(const float* __restrict__ kern,
                            const float* __restrict__ bias,
                            float* __restrict__ out) {
    int lane = threadIdx.x & 31;
    int q    = lane & 15;     // f-quad 0..15
    int nsub = lane >> 4;     // 0..1

    float4 k4[T_];
    #pragma unroll
    for (int t = 0; t < T_; ++t)
        k4[t] = __ldg(reinterpret_cast<const float4*>(kern) + t * 16 + q);
    float4 b4 = __ldg(reinterpret_cast<const float4*>(bias) + q);

    int warp = (blockIdx.x * blockDim.x + threadIdx.x) >> 5;   // 0..16383
    int n0 = warp * 2 + nsub;

    float4* arow = reinterpret_cast<float4*>(g_agg) + (size_t)n0 * 2;
    float4 a0 = __ldcg(arow);
    float4 a1 = __ldcg(arow + 1);

    #pragma unroll
    for (int i = 0; i < GEMM_ITERS; ++i) {
        int n = n0 + i * GEMM_WARPS * 2;
        float4* crow = reinterpret_cast<float4*>(g_agg) + (size_t)n * 2;

        float4 na0, na1;
        if (i + 1 < GEMM_ITERS) {
            const float4* nrow = reinterpret_cast<const float4*>(g_agg)
                               + ((size_t)n + GEMM_WARPS * 2) * 2;
            na0 = __ldcg(nrow);
            na1 = __ldcg(nrow + 1);
        }

        float4 acc = b4;
        acc.x = fmaf(a0.x, k4[0].x, acc.x); acc.y = fmaf(a0.x, k4[0].y, acc.y);
        acc.z = fmaf(a0.x, k4[0].z, acc.z); acc.w = fmaf(a0.x, k4[0].w, acc.w);
        acc.x = fmaf(a0.y, k4[1].x, acc.x); acc.y = fmaf(a0.y, k4[1].y, acc.y);
        acc.z = fmaf(a0.y, k4[1].z, acc.z); acc.w = fmaf(a0.y, k4[1].w, acc.w);
        acc.x = fmaf(a0.z, k4[2].x, acc.x); acc.y = fmaf(a0.z, k4[2].y, acc.y);
        acc.z = fmaf(a0.z, k4[2].z, acc.z); acc.w = fmaf(a0.z, k4[2].w, acc.w);
        acc.x = fmaf(a0.w, k4[3].x, acc.x); acc.y = fmaf(a0.w, k4[3].y, acc.y);
        acc.z = fmaf(a0.w, k4[3].z, acc.z); acc.w = fmaf(a0.w, k4[3].w, acc.w);
        acc.x = fmaf(a1.x, k4[4].x, acc.x); acc.y = fmaf(a1.x, k4[4].y, acc.y);
        acc.z = fmaf(a1.x, k4[4].z, acc.z); acc.w = fmaf(a1.x, k4[4].w, acc.w);
        acc.x = fmaf(a1.y, k4[5].x, acc.x); acc.y = fmaf(a1.y, k4[5].y, acc.y);
        acc.z = fmaf(a1.y, k4[5].z, acc.z); acc.w = fmaf(a1.y, k4[5].w, acc.w);
        acc.x = fmaf(a1.z, k4[6].x, acc.x); acc.y = fmaf(a1.z, k4[6].y, acc.y);
        acc.z = fmaf(a1.z, k4[6].z, acc.z); acc.w = fmaf(a1.z, k4[6].w, acc.w);
        acc.x = fmaf(a1.w, k4[7].x, acc.x); acc.y = fmaf(a1.w, k4[7].y, acc.y);
        acc.z = fmaf(a1.w, k4[7].z, acc.z); acc.w = fmaf(a1.w, k4[7].w, acc.w);

        __stcs(reinterpret_cast<float4*>(out) + (size_t)n * 16 + q, acc);

        // consume-and-zero this node's 32B agg row (q selects which half).
        __syncwarp();
        if (q < 2)
            crow[q] = make_float4(0.f, 0.f, 0.f, 0.f);

        a0 = na0;
        a1 = na1;
    }
}

// ---------------------------------------------------------------------------
// Launch contract — inputs resolved BY ELEMENT COUNT (robust to whether the
// scalar `out_size` occupies an input slot):
//   edge_features:  T*E = 67108864 f32
//   sparse_indices: E*2 = 16777216 i32
//   kernel:         T*F = 512 f32
//   bias:           F   = 64 f32
// Output: N*F f32.
// ---------------------------------------------------------------------------
extern "C" void kernel_launch(void* const* d_in, const int* in_sizes, int n_in,
                              void* d_out, int out_size) {
    const float* feat = nullptr;
    const int2*  idx  = nullptr;
    const float* kern = nullptr;
    const float* bias = nullptr;

    for (int i = 0; i < n_in; ++i) {
        long long s = in_sizes[i];
        if      (s == (long long)T_ * E_) feat = (const float*)d_in[i];
        else if (s == (long long)2 * E_)  idx  = (const int2*)d_in[i];
        else if (s == T_ * F_)            kern = (const float*)d_in[i];
        else if (s == F_)                 bias = (const float*)d_in[i];
    }
    if (!feat) feat = (const float*)d_in[0];
    if (!idx)  idx  = (const int2*)d_in[1];
    if (!kern) kern = (const float*)d_in[n_in >= 5 ? 3 : 2];
    if (!bias) bias = (const float*)d_in[n_in >= 5 ? 4 : 3];

    float* out = (float*)d_out;
    (void)out_size;

    scatter_kernel<<<E_ / 256, 256>>>(feat, idx);
    gemm_kernel<<<GEMM_WARPS * 32 / 256, 256>>>(kern, bias, out);
}

// round 11
// speedup vs baseline: 1.2425x; 1.2425x over previous
#include <cuda_runtime.h>
#include <cstdint>

// Problem constants (fixed by the dataset)
#define T_ 8
#define E_ 8388608
#define N_ 262144
#define F_ 64

// 8 MB scratch for segment sums, layout agg[n][t] row-major (32B per node).
__device__ float g_agg[(size_t)N_ * T_];

// ---------------------------------------------------------------------------
// Kernel 1: zero agg right before scatter. Under the 1-line-per-edge RED
// shape, warm dirty L2 lines save ~20us in scatter (measured R9 vs R10) —
// far more than this kernel's ~5us cost. Load-bearing; do not remove.
// ---------------------------------------------------------------------------
__global__ void zero_agg_kernel() {
    int i = blockIdx.x * blockDim.x + threadIdx.x;   // N_*T_/4 = 524288 float4s
    reinterpret_cast<float4*>(g_agg)[i] = make_float4(0.f, 0.f, 0.f, 0.f);
}

// ---------------------------------------------------------------------------
// Kernel 2: scatter-add. Warp = 32 edges. Lane pair (2p, 2p+1) handles edges
// eA, eB: even lane covers feature planes 0..3, odd lane 4..7, each loading
// float2 {eA,eB} per plane (fully-consumed 128B lines). Rows swapped via
// SHFL. Each RED instruction covers 16 edges' full 32B agg rows -> 1 line-
// wavefront per edge (the minimum with random rows). At measured floor.
// ---------------------------------------------------------------------------
__global__ void scatter_kernel(const float* __restrict__ feat,
                               const int2* __restrict__ idx) {
    int tid   = blockIdx.x * blockDim.x + threadIdx.x;
    int lane  = threadIdx.x & 31;
    int h     = lane & 1;                 // 0: planes 0..3, 1: planes 4..7
    int ebase = (tid >> 5) * 32;          // warp's first edge
    int eA    = ebase + (lane & ~1);      // pair's even edge

    int2 rc = __ldcs(&idx[ebase + lane]); // coalesced 256B/warp
    int row = rc.x & (N_ - 1);            // pow2 mask: no-op for valid rows

    int rA = __shfl_sync(0xffffffffu, row, lane & ~1);
    int rB = __shfl_sync(0xffffffffu, row, lane | 1);

    size_t plane = (size_t)(4 * h) * E_ + eA;
    float2 l0 = __ldcs(reinterpret_cast<const float2*>(feat + plane));
    float2 l1 = __ldcs(reinterpret_cast<const float2*>(feat + plane + (size_t)E_));
    float2 l2 = __ldcs(reinterpret_cast<const float2*>(feat + plane + (size_t)2 * E_));
    float2 l3 = __ldcs(reinterpret_cast<const float2*>(feat + plane + (size_t)3 * E_));

    float* dA = g_agg + (size_t)rA * T_ + 4 * h;
    asm volatile("red.global.add.v4.f32 [%0], {%1,%2,%3,%4};"
                 :: "l"(dA), "f"(l0.x), "f"(l1.x), "f"(l2.x), "f"(l3.x) : "memory");

    float* dB = g_agg + (size_t)rB * T_ + 4 * h;
    asm volatile("red.global.add.v4.f32 [%0], {%1,%2,%3,%4};"
                 :: "l"(dB), "f"(l0.y), "f"(l1.y), "f"(l2.y), "f"(l3.y) : "memory");
}

// ---------------------------------------------------------------------------
// Kernel 3 (GEMM): out[n,f] = sum_t agg[n,t]*K[t,f] + bias[f].
// 16384 warps; K slice in registers (loaded once per warp), 8 iters x 2
// nodes with the next agg row prefetched before computing the current one.
// No zeroing here (the explicit zero kernel owns that).
// ---------------------------------------------------------------------------
#define GEMM_WARPS 16384
#define GEMM_ITERS (N_ / (GEMM_WARPS * 2))   // 8

__global__ void gemm_kernel(const float* __restrict__ kern,
                            const float* __restrict__ bias,
                            float* __restrict__ out) {
    int lane = threadIdx.x & 31;
    int q    = lane & 15;     // f-quad 0..15
    int nsub = lane >> 4;     // 0..1

    float4 k4[T_];
    #pragma unroll
    for (int t = 0; t < T_; ++t)
        k4[t] = __ldg(reinterpret_cast<const float4*>(kern) + t * 16 + q);
    float4 b4 = __ldg(reinterpret_cast<const float4*>(bias) + q);

    int warp = (blockIdx.x * blockDim.x + threadIdx.x) >> 5;   // 0..16383
    int n0 = warp * 2 + nsub;

    const float4* arow = reinterpret_cast<const float4*>(g_agg) + (size_t)n0 * 2;
    float4 a0 = __ldcg(arow);
    float4 a1 = __ldcg(arow + 1);

    #pragma unroll
    for (int i = 0; i < GEMM_ITERS; ++i) {
        int n = n0 + i * GEMM_WARPS * 2;

        float4 na0, na1;
        if (i + 1 < GEMM_ITERS) {
            const float4* nrow = reinterpret_cast<const float4*>(g_agg)
                               + ((size_t)n + GEMM_WARPS * 2) * 2;
            na0 = __ldcg(nrow);
            na1 = __ldcg(nrow + 1);
        }

        float4 acc = b4;
        acc.x = fmaf(a0.x, k4[0].x, acc.x); acc.y = fmaf(a0.x, k4[0].y, acc.y);
        acc.z = fmaf(a0.x, k4[0].z, acc.z); acc.w = fmaf(a0.x, k4[0].w, acc.w);
        acc.x = fmaf(a0.y, k4[1].x, acc.x); acc.y = fmaf(a0.y, k4[1].y, acc.y);
        acc.z = fmaf(a0.y, k4[1].z, acc.z); acc.w = fmaf(a0.y, k4[1].w, acc.w);
        acc.x = fmaf(a0.z, k4[2].x, acc.x); acc.y = fmaf(a0.z, k4[2].y, acc.y);
        acc.z = fmaf(a0.z, k4[2].z, acc.z); acc.w = fmaf(a0.z, k4[2].w, acc.w);
        acc.x = fmaf(a0.w, k4[3].x, acc.x); acc.y = fmaf(a0.w, k4[3].y, acc.y);
        acc.z = fmaf(a0.w, k4[3].z, acc.z); acc.w = fmaf(a0.w, k4[3].w, acc.w);
        acc.x = fmaf(a1.x, k4[4].x, acc.x); acc.y = fmaf(a1.x, k4[4].y, acc.y);
        acc.z = fmaf(a1.x, k4[4].z, acc.z); acc.w = fmaf(a1.x, k4[4].w, acc.w);
        acc.x = fmaf(a1.y, k4[5].x, acc.x); acc.y = fmaf(a1.y, k4[5].y, acc.y);
        acc.z = fmaf(a1.y, k4[5].z, acc.z); acc.w = fmaf(a1.y, k4[5].w, acc.w);
        acc.x = fmaf(a1.z, k4[6].x, acc.x); acc.y = fmaf(a1.z, k4[6].y, acc.y);
        acc.z = fmaf(a1.z, k4[6].z, acc.z); acc.w = fmaf(a1.z, k4[6].w, acc.w);
        acc.x = fmaf(a1.w, k4[7].x, acc.x); acc.y = fmaf(a1.w, k4[7].y, acc.y);
        acc.z = fmaf(a1.w, k4[7].z, acc.z); acc.w = fmaf(a1.w, k4[7].w, acc.w);

        __stcs(reinterpret_cast<float4*>(out) + (size_t)n * 16 + q, acc);

        a0 = na0;
        a1 = na1;
    }
}

// ---------------------------------------------------------------------------
// Launch contract — inputs resolved BY ELEMENT COUNT (robust to whether the
// scalar `out_size` occupies an input slot):
//   edge_features:  T*E = 67108864 f32
//   sparse_indices: E*2 = 16777216 i32
//   kernel:         T*F = 512 f32
//   bias:           F   = 64 f32
// Output: N*F f32.
// ---------------------------------------------------------------------------
extern "C" void kernel_launch(void* const* d_in, const int* in_sizes, int n_in,
                              void* d_out, int out_size) {
    const float* feat = nullptr;
    const int2*  idx  = nullptr;
    const float* kern = nullptr;
    const float* bias = nullptr;

    for (int i = 0; i < n_in; ++i) {
        long long s = in_sizes[i];
        if      (s == (long long)T_ * E_) feat = (const float*)d_in[i];
        else if (s == (long long)2 * E_)  idx  = (const int2*)d_in[i];
        else if (s == T_ * F_)            kern = (const float*)d_in[i];
        else if (s == F_)                 bias = (const float*)d_in[i];
    }
    if (!feat) feat = (const float*)d_in[0];
    if (!idx)  idx  = (const int2*)d_in[1];
    if (!kern) kern = (const float*)d_in[n_in >= 5 ? 3 : 2];
    if (!bias) bias = (const float*)d_in[n_in >= 5 ? 4 : 3];

    float* out = (float*)d_out;
    (void)out_size;

    zero_agg_kernel<<<(N_ * T_ / 4) / 256, 256>>>();
    scatter_kernel<<<E_ / 256, 256>>>(feat, idx);
    gemm_kernel<<<GEMM_WARPS * 32 / 256, 256>>>(kern, bias, out);
}